// round 3
// baseline (speedup 1.0000x reference)
#include <cuda_runtime.h>

__device__ __forceinline__ float fast_tanh(float t) {
    float r;
    asm("tanh.approx.f32 %0, %1;" : "=f"(r) : "f"(t));
    return r;
}

struct SParams {
    float w1a[8], w1b[8], b1[8], m1[8];   // layer 1: h = x0*w1a + x1*w1b + b1 ; tanh arg = m1*h (m1 = 0.5*c1)
    float w2[8][4];                        // layer 2 weights (a1 folded in)
    float b2[4], m2[4];                    // m2 = 0.5*c2
    float w3[4], b3;                       // layer 3 (a2 folded into w3)
};

__device__ __forceinline__ float row_eval(float x0, float x1, const SParams& P) {
    float g[8];
#pragma unroll
    for (int j = 0; j < 8; j++) {
        float h = fmaf(x0, P.w1a[j], fmaf(x1, P.w1b[j], P.b1[j]));
        float t = fast_tanh(P.m1[j] * h);
        float s = fmaf(t, 0.5f, 0.5f);          // FFMA-imm form (rt=1)
        g[j] = h * s;
    }
    float o = P.b3;
#pragma unroll
    for (int j = 0; j < 4; j++) {
        float z = P.b2[j];
#pragma unroll
        for (int i = 0; i < 8; i++)
            z = fmaf(g[i], P.w2[i][j], z);
        float t = fast_tanh(P.m2[j] * z);
        float s = fmaf(t, 0.5f, 0.5f);
        o = fmaf(z * s, P.w3[j], o);
    }
    return o;
}

__global__ __launch_bounds__(256, 4)
void moth_mlp_kernel(const float4* __restrict__ x4,
                     const float* __restrict__ W1, const float* __restrict__ b1,
                     const float* __restrict__ a1, const float* __restrict__ c1,
                     const float* __restrict__ W2, const float* __restrict__ b2,
                     const float* __restrict__ a2, const float* __restrict__ c2,
                     const float* __restrict__ W3, const float* __restrict__ b3,
                     float2* __restrict__ out2,
                     int npairs, int nrows)
{
    __shared__ SParams P;
    {
        int t = threadIdx.x;
        if (t < 8) {
            P.w1a[t] = W1[t];
            P.w1b[t] = W1[8 + t];
            P.b1[t]  = b1[t];
            P.m1[t]  = 0.5f * c1[t];
            float a = a1[t];
#pragma unroll
            for (int j = 0; j < 4; j++)
                P.w2[t][j] = a * W2[t * 4 + j];
        }
        if (t < 4) {
            P.b2[t] = b2[t];
            P.m2[t] = 0.5f * c2[t];
            P.w3[t] = a2[t] * W3[t];
        }
        if (t == 0) P.b3 = b3[0];
    }
    __syncthreads();

    const int stride = gridDim.x * blockDim.x;
    int tid = blockIdx.x * blockDim.x + threadIdx.x;

    for (int p = tid; p < npairs; p += stride) {
        float4 xx = x4[p];                 // two rows: (x,y) and (z,w)
        float oa = row_eval(xx.x, xx.y, P);
        float ob = row_eval(xx.z, xx.w, P);
        out2[p] = make_float2(oa, ob);
    }

    // odd-row tail (not hit for B = 8388608, kept for safety)
    if ((nrows & 1) && tid == 0) {
        const float2* x2 = reinterpret_cast<const float2*>(x4);
        float2 xr = x2[nrows - 1];
        reinterpret_cast<float*>(out2)[nrows - 1] = row_eval(xr.x, xr.y, P);
    }
}

extern "C" void kernel_launch(void* const* d_in, const int* in_sizes, int n_in,
                              void* d_out, int out_size)
{
    const float4* x4 = (const float4*)d_in[0];
    const float* W1 = (const float*)d_in[1];
    const float* b1 = (const float*)d_in[2];
    const float* a1 = (const float*)d_in[3];
    const float* c1 = (const float*)d_in[4];
    const float* W2 = (const float*)d_in[5];
    const float* b2 = (const float*)d_in[6];
    const float* a2 = (const float*)d_in[7];
    const float* c2 = (const float*)d_in[8];
    const float* W3 = (const float*)d_in[9];
    const float* b3 = (const float*)d_in[10];

    int nrows = in_sizes[0] / 2;   // x is [B, 2]
    int npairs = nrows / 2;

    const int threads = 256;
    const int blocks = 1184;       // 148 SMs * 8; grid-stride

    moth_mlp_kernel<<<blocks, threads>>>(x4, W1, b1, a1, c1, W2, b2, a2, c2, W3, b3,
                                         (float2*)d_out, npairs, nrows);
}

// round 6
// speedup vs baseline: 2.4842x; 2.4842x over previous
#include <cuda_runtime.h>

typedef unsigned long long ull;

__device__ __forceinline__ float fast_tanh(float t) {
    float r;
    asm("tanh.approx.f32 %0, %1;" : "=f"(r) : "f"(t));
    return r;
}
__device__ __forceinline__ ull pack2(float lo, float hi) {
    ull r;
    asm("mov.b64 %0, {%1, %2};" : "=l"(r) : "f"(lo), "f"(hi));
    return r;
}
__device__ __forceinline__ ull splat2(float v) {
    ull r;
    asm("mov.b64 %0, {%1, %1};" : "=l"(r) : "f"(v));
    return r;
}
__device__ __forceinline__ void unpack2(ull v, float& lo, float& hi) {
    asm("mov.b64 {%0, %1}, %2;" : "=f"(lo), "=f"(hi) : "l"(v));
}
__device__ __forceinline__ ull ffma2(ull a, ull b, ull c) {
    ull d;
    asm("fma.rn.f32x2 %0, %1, %2, %3;" : "=l"(d) : "l"(a), "l"(b), "l"(c));
    return d;
}
__device__ __forceinline__ ull fmul2(ull a, ull b) {
    ull d;
    asm("mul.rn.f32x2 %0, %1, %2;" : "=l"(d) : "l"(a), "l"(b));
    return d;
}

struct Pr {
    ull w1a[4], w1b[4], b1[4], m1[4];   // layer-1 packed over j-pairs; m1 = 0.5*c1
    ull w2t[4][2];                      // hmm placeholder (see fold) -- [j][qpair over i]... replaced below
    ull w2[4][4];                       // w2[j][q] = pack(a1[2q]*W2[2q][j], a1[2q+1]*W2[2q+1][j])
    float b2[4], m2[4];                 // m2 = 0.5*c2
    float w3[4], b3;                    // a2 folded into w3
};

__device__ __forceinline__ float row_eval(float x0, float x1, const Pr& p) {
    ull x0p = splat2(x0), x1p = splat2(x1);
    ull h[4], gp[4];
#pragma unroll
    for (int q = 0; q < 4; q++)
        h[q] = ffma2(x0p, p.w1a[q], ffma2(x1p, p.w1b[q], p.b1[q]));
#pragma unroll
    for (int q = 0; q < 4; q++) {
        ull t2 = fmul2(p.m1[q], h[q]);
        float t0, t1; unpack2(t2, t0, t1);
        float s0 = fmaf(fast_tanh(t0), 0.5f, 0.5f);   // sigmoid(c*h) = 0.5*tanh(0.5*c*h)+0.5
        float s1 = fmaf(fast_tanh(t1), 0.5f, 0.5f);
        gp[q] = fmul2(h[q], pack2(s0, s1));            // g = h * sigmoid (a1 folded into W2)
    }
    float o = p.b3;
#pragma unroll
    for (int j = 0; j < 4; j++) {
        ull acc = fmul2(gp[0], p.w2[j][0]);
        acc = ffma2(gp[1], p.w2[j][1], acc);
        acc = ffma2(gp[2], p.w2[j][2], acc);
        acc = ffma2(gp[3], p.w2[j][3], acc);
        float lo, hi; unpack2(acc, lo, hi);
        float zj = (p.b2[j] + lo) + hi;
        float s = fmaf(fast_tanh(p.m2[j] * zj), 0.5f, 0.5f);
        o = fmaf(zj * s, p.w3[j], o);                  // a2 folded into w3
    }
    return o;
}

__global__ __launch_bounds__(256)
void moth_mlp_kernel(const float4* __restrict__ x4,
                     const float* __restrict__ W1, const float* __restrict__ b1,
                     const float* __restrict__ a1, const float* __restrict__ c1,
                     const float* __restrict__ W2, const float* __restrict__ b2,
                     const float* __restrict__ a2, const float* __restrict__ c2,
                     const float* __restrict__ W3, const float* __restrict__ b3,
                     float2* __restrict__ out2,
                     int npairs, int nrows)
{
    Pr p;
#pragma unroll
    for (int q = 0; q < 4; q++) {
        p.w1a[q] = pack2(W1[2*q],     W1[2*q + 1]);
        p.w1b[q] = pack2(W1[8 + 2*q], W1[8 + 2*q + 1]);
        p.b1[q]  = pack2(b1[2*q],     b1[2*q + 1]);
        p.m1[q]  = pack2(0.5f * c1[2*q], 0.5f * c1[2*q + 1]);
    }
#pragma unroll
    for (int j = 0; j < 4; j++) {
#pragma unroll
        for (int q = 0; q < 4; q++) {
            int i0 = 2*q, i1 = 2*q + 1;
            p.w2[j][q] = pack2(a1[i0] * W2[i0*4 + j], a1[i1] * W2[i1*4 + j]);
        }
        p.b2[j] = b2[j];
        p.m2[j] = 0.5f * c2[j];
        p.w3[j] = a2[j] * W3[j];
    }
    p.b3 = b3[0];

    const int stride = gridDim.x * blockDim.x;
    int tid = blockIdx.x * blockDim.x + threadIdx.x;

    for (int pi = tid; pi < npairs; pi += stride) {
        float4 xx = x4[pi];                 // two rows: (x,y) and (z,w)
        float oa = row_eval(xx.x, xx.y, p);
        float ob = row_eval(xx.z, xx.w, p);
        out2[pi] = make_float2(oa, ob);
    }

    // odd-row tail (not hit for B = 8388608, kept for safety)
    if ((nrows & 1) && tid == 0) {
        const float2* x2 = reinterpret_cast<const float2*>(x4);
        float2 xr = x2[nrows - 1];
        reinterpret_cast<float*>(out2)[nrows - 1] = row_eval(xr.x, xr.y, p);
    }
}

extern "C" void kernel_launch(void* const* d_in, const int* in_sizes, int n_in,
                              void* d_out, int out_size)
{
    const float4* x4 = (const float4*)d_in[0];
    const float* W1 = (const float*)d_in[1];
    const float* b1 = (const float*)d_in[2];
    const float* a1 = (const float*)d_in[3];
    const float* c1 = (const float*)d_in[4];
    const float* W2 = (const float*)d_in[5];
    const float* b2 = (const float*)d_in[6];
    const float* a2 = (const float*)d_in[7];
    const float* c2 = (const float*)d_in[8];
    const float* W3 = (const float*)d_in[9];
    const float* b3 = (const float*)d_in[10];

    int nrows = in_sizes[0] / 2;   // x is [B, 2]
    int npairs = nrows / 2;

    const int threads = 256;
    const int blocks = 1184;       // 148 SMs * 8; grid-stride

    moth_mlp_kernel<<<blocks, threads>>>(x4, W1, b1, a1, c1, W2, b2, a2, c2, W3, b3,
                                         (float2*)d_out, npairs, nrows);
}

// round 7
// speedup vs baseline: 2.6226x; 1.0557x over previous
#include <cuda_runtime.h>

typedef unsigned long long ull;

__device__ __forceinline__ float fast_tanh(float t) {
    float r;
    asm("tanh.approx.f32 %0, %1;" : "=f"(r) : "f"(t));
    return r;
}
__device__ __forceinline__ ull pack2(float lo, float hi) {
    ull r;
    asm("mov.b64 %0, {%1, %2};" : "=l"(r) : "f"(lo), "f"(hi));
    return r;
}
__device__ __forceinline__ ull splat2(float v) {
    ull r;
    asm("mov.b64 %0, {%1, %1};" : "=l"(r) : "f"(v));
    return r;
}
__device__ __forceinline__ void unpack2(ull v, float& lo, float& hi) {
    asm("mov.b64 {%0, %1}, %2;" : "=f"(lo), "=f"(hi) : "l"(v));
}
__device__ __forceinline__ ull ffma2(ull a, ull b, ull c) {
    ull d;
    asm("fma.rn.f32x2 %0, %1, %2, %3;" : "=l"(d) : "l"(a), "l"(b), "l"(c));
    return d;
}
__device__ __forceinline__ ull fmul2(ull a, ull b) {
    ull d;
    asm("mul.rn.f32x2 %0, %1, %2;" : "=l"(d) : "l"(a), "l"(b));
    return d;
}
__device__ __forceinline__ ull fadd2(ull a, ull b) {
    ull d;
    asm("add.rn.f32x2 %0, %1, %2;" : "=l"(d) : "l"(a), "l"(b));
    return d;
}

struct Pr {
    ull w1a[4], w1b[4], b1[4], m1[4];   // layer-1 packed over j-pairs; m1 = 0.5*c1
    ull w2[4][4];                       // w2[j][q] = pack(a1[2q]*W2[2q][j], a1[2q+1]*W2[2q+1][j])
    ull b2s[4], m2s[4], w3s[4];         // row-pair splats; m2 = 0.5*c2, w3 has a2 folded
    ull b3s, half2;                     // splat(b3), splat(0.5)
};

// layer 1 for one row: produce g[4] (8 features as 4 f32x2 pairs)
__device__ __forceinline__ void layer1(float x0, float x1, const Pr& p, ull g[4]) {
    ull x0p = splat2(x0), x1p = splat2(x1);
#pragma unroll
    for (int q = 0; q < 4; q++) {
        ull h   = ffma2(x0p, p.w1a[q], ffma2(x1p, p.w1b[q], p.b1[q]));
        ull arg = fmul2(p.m1[q], h);
        float t0, t1; unpack2(arg, t0, t1);
        ull tp = pack2(fast_tanh(t0), fast_tanh(t1));
        ull sp = ffma2(tp, p.half2, p.half2);    // sigmoid = 0.5*tanh + 0.5 (packed)
        g[q] = fmul2(h, sp);                     // a1 folded into W2
    }
}

// evaluate both rows of a pair; epilogue packed over (rowA, rowB)
__device__ __forceinline__ float2 pair_eval(float4 xx, const Pr& p) {
    ull gA[4], gB[4];
    layer1(xx.x, xx.y, p, gA);
    layer1(xx.z, xx.w, p, gB);

    ull op = p.b3s;                              // packed output accumulator (rowA, rowB)
#pragma unroll
    for (int j = 0; j < 4; j++) {
        ull accA = fmul2(gA[0], p.w2[j][0]);
        ull accB = fmul2(gB[0], p.w2[j][0]);
#pragma unroll
        for (int q = 1; q < 4; q++) {
            accA = ffma2(gA[q], p.w2[j][q], accA);
            accB = ffma2(gB[q], p.w2[j][q], accB);
        }
        float alo, ahi, blo, bhi;
        unpack2(accA, alo, ahi);
        unpack2(accB, blo, bhi);
        ull zp = fadd2(fadd2(pack2(alo, blo), pack2(ahi, bhi)), p.b2s[j]);  // (zA_j, zB_j)
        ull argp = fmul2(p.m2s[j], zp);
        float t0, t1; unpack2(argp, t0, t1);
        ull tp = pack2(fast_tanh(t0), fast_tanh(t1));
        ull sp = ffma2(tp, p.half2, p.half2);
        op = ffma2(fmul2(zp, sp), p.w3s[j], op); // o += w3 * z * sigmoid  (a2 folded)
    }
    float oA, oB; unpack2(op, oA, oB);
    return make_float2(oA, oB);
}

__global__ __launch_bounds__(128)
void moth_mlp_kernel(const float4* __restrict__ x4,
                     const float* __restrict__ W1, const float* __restrict__ b1,
                     const float* __restrict__ a1, const float* __restrict__ c1,
                     const float* __restrict__ W2, const float* __restrict__ b2,
                     const float* __restrict__ a2, const float* __restrict__ c2,
                     const float* __restrict__ W3, const float* __restrict__ b3,
                     float2* __restrict__ out2,
                     int npairs, int nrows)
{
    Pr p;
#pragma unroll
    for (int q = 0; q < 4; q++) {
        p.w1a[q] = pack2(W1[2*q],     W1[2*q + 1]);
        p.w1b[q] = pack2(W1[8 + 2*q], W1[8 + 2*q + 1]);
        p.b1[q]  = pack2(b1[2*q],     b1[2*q + 1]);
        p.m1[q]  = pack2(0.5f * c1[2*q], 0.5f * c1[2*q + 1]);
    }
#pragma unroll
    for (int j = 0; j < 4; j++) {
#pragma unroll
        for (int q = 0; q < 4; q++) {
            int i0 = 2*q, i1 = 2*q + 1;
            p.w2[j][q] = pack2(a1[i0] * W2[i0*4 + j], a1[i1] * W2[i1*4 + j]);
        }
        p.b2s[j] = splat2(b2[j]);
        p.m2s[j] = splat2(0.5f * c2[j]);
        p.w3s[j] = splat2(a2[j] * W3[j]);
    }
    p.b3s  = splat2(b3[0]);
    p.half2 = splat2(0.5f);

    const int stride = gridDim.x * blockDim.x;
    int tid = blockIdx.x * blockDim.x + threadIdx.x;

    for (int pi = tid; pi < npairs; pi += stride)
        out2[pi] = pair_eval(x4[pi], p);

    // odd-row tail (not hit for B = 8388608, kept for safety)
    if ((nrows & 1) && tid == 0) {
        const float2* x2 = reinterpret_cast<const float2*>(x4);
        float2 xr = x2[nrows - 1];
        float2 r = pair_eval(make_float4(xr.x, xr.y, xr.x, xr.y), p);
        reinterpret_cast<float*>(out2)[nrows - 1] = r.x;
    }
}

extern "C" void kernel_launch(void* const* d_in, const int* in_sizes, int n_in,
                              void* d_out, int out_size)
{
    const float4* x4 = (const float4*)d_in[0];
    const float* W1 = (const float*)d_in[1];
    const float* b1 = (const float*)d_in[2];
    const float* a1 = (const float*)d_in[3];
    const float* c1 = (const float*)d_in[4];
    const float* W2 = (const float*)d_in[5];
    const float* b2 = (const float*)d_in[6];
    const float* a2 = (const float*)d_in[7];
    const float* c2 = (const float*)d_in[8];
    const float* W3 = (const float*)d_in[9];
    const float* b3 = (const float*)d_in[10];

    int nrows = in_sizes[0] / 2;   // x is [B, 2]
    int npairs = nrows / 2;

    const int threads = 128;
    const int blocks = 2368;       // 148 SMs * 16; grid-stride

    moth_mlp_kernel<<<blocks, threads>>>(x4, W1, b1, a1, c1, W2, b2, a2, c2, W3, b3,
                                         (float2*)d_out, npairs, nrows);
}

// round 8
// speedup vs baseline: 2.7500x; 1.0486x over previous
#include <cuda_runtime.h>

typedef unsigned long long ull;

__device__ __forceinline__ float fast_tanh(float t) {
    float r;
    asm("tanh.approx.f32 %0, %1;" : "=f"(r) : "f"(t));
    return r;
}
__device__ __forceinline__ ull pack2(float lo, float hi) {
    ull r;
    asm("mov.b64 %0, {%1, %2};" : "=l"(r) : "f"(lo), "f"(hi));
    return r;
}
__device__ __forceinline__ ull splat2(float v) {
    ull r;
    asm("mov.b64 %0, {%1, %1};" : "=l"(r) : "f"(v));
    return r;
}
__device__ __forceinline__ void unpack2(ull v, float& lo, float& hi) {
    asm("mov.b64 {%0, %1}, %2;" : "=f"(lo), "=f"(hi) : "l"(v));
}
__device__ __forceinline__ ull ffma2(ull a, ull b, ull c) {
    ull d;
    asm("fma.rn.f32x2 %0, %1, %2, %3;" : "=l"(d) : "l"(a), "l"(b), "l"(c));
    return d;
}
__device__ __forceinline__ ull fmul2(ull a, ull b) {
    ull d;
    asm("mul.rn.f32x2 %0, %1, %2;" : "=l"(d) : "l"(a), "l"(b));
    return d;
}
__device__ __forceinline__ ull fadd2(ull a, ull b) {
    ull d;
    asm("add.rn.f32x2 %0, %1, %2;" : "=l"(d) : "l"(a), "l"(b));
    return d;
}

struct Pr {
    ull w1a[4], w1b[4], b1[4], m1[4];   // layer-1 packed over j-pairs; m1 = 0.5*c1
    ull w2[4][4];                       // w2[j][q] = pack(a1[2q]*W2[2q][j], a1[2q+1]*W2[2q+1][j])
    ull b2s[4], m2s[4], w3s[4];         // row-pair splats; m2 = 0.5*c2, w3 has a2 folded
    ull b3s, half2;                     // splat(b3), splat(0.5)
};

// layer 1 for one row: produce g[4] (8 features as 4 f32x2 pairs)
__device__ __forceinline__ void layer1(float x0, float x1, const Pr& p, ull g[4]) {
    ull x0p = splat2(x0), x1p = splat2(x1);
#pragma unroll
    for (int q = 0; q < 4; q++) {
        ull h   = ffma2(x0p, p.w1a[q], ffma2(x1p, p.w1b[q], p.b1[q]));
        ull arg = fmul2(p.m1[q], h);
        float t0, t1; unpack2(arg, t0, t1);
        ull tp = pack2(fast_tanh(t0), fast_tanh(t1));
        ull sp = ffma2(tp, p.half2, p.half2);    // sigmoid = 0.5*tanh + 0.5 (packed)
        g[q] = fmul2(h, sp);                     // a1 folded into W2
    }
}

// epilogue for one row-pair: layer2 + layer3, packed over (rowA, rowB)
__device__ __forceinline__ float2 epilogue(const ull gA[4], const ull gB[4], const Pr& p) {
    ull op = p.b3s;                              // packed output accumulator (rowA, rowB)
#pragma unroll
    for (int j = 0; j < 4; j++) {
        ull accA = fmul2(gA[0], p.w2[j][0]);
        ull accB = fmul2(gB[0], p.w2[j][0]);
#pragma unroll
        for (int q = 1; q < 4; q++) {
            accA = ffma2(gA[q], p.w2[j][q], accA);
            accB = ffma2(gB[q], p.w2[j][q], accB);
        }
        float alo, ahi, blo, bhi;
        unpack2(accA, alo, ahi);
        unpack2(accB, blo, bhi);
        ull zp = fadd2(fadd2(pack2(alo, blo), pack2(ahi, bhi)), p.b2s[j]);  // (zA_j, zB_j)
        ull argp = fmul2(p.m2s[j], zp);
        float t0, t1; unpack2(argp, t0, t1);
        ull tp = pack2(fast_tanh(t0), fast_tanh(t1));
        ull sp = ffma2(tp, p.half2, p.half2);
        op = ffma2(fmul2(zp, sp), p.w3s[j], op); // o += w3 * z * sigmoid  (a2 folded)
    }
    float oA, oB; unpack2(op, oA, oB);
    return make_float2(oA, oB);
}

__global__ __launch_bounds__(128)
void moth_mlp_kernel(const float4* __restrict__ x4,
                     const float* __restrict__ W1, const float* __restrict__ b1,
                     const float* __restrict__ a1, const float* __restrict__ c1,
                     const float* __restrict__ W2, const float* __restrict__ b2,
                     const float* __restrict__ a2, const float* __restrict__ c2,
                     const float* __restrict__ W3, const float* __restrict__ b3,
                     float2* __restrict__ out2,
                     int npairs, int nrows)
{
    Pr p;
#pragma unroll
    for (int q = 0; q < 4; q++) {
        p.w1a[q] = pack2(W1[2*q],     W1[2*q + 1]);
        p.w1b[q] = pack2(W1[8 + 2*q], W1[8 + 2*q + 1]);
        p.b1[q]  = pack2(b1[2*q],     b1[2*q + 1]);
        p.m1[q]  = pack2(0.5f * c1[2*q], 0.5f * c1[2*q + 1]);
    }
#pragma unroll
    for (int j = 0; j < 4; j++) {
#pragma unroll
        for (int q = 0; q < 4; q++) {
            int i0 = 2*q, i1 = 2*q + 1;
            p.w2[j][q] = pack2(a1[i0] * W2[i0*4 + j], a1[i1] * W2[i1*4 + j]);
        }
        p.b2s[j] = splat2(b2[j]);
        p.m2s[j] = splat2(0.5f * c2[j]);
        p.w3s[j] = splat2(a2[j] * W3[j]);
    }
    p.b3s  = splat2(b3[0]);
    p.half2 = splat2(0.5f);

    const int stride = gridDim.x * blockDim.x;
    int tid = blockIdx.x * blockDim.x + threadIdx.x;

    int nquads = npairs >> 1;          // 2 pairs (4 rows) per iteration

    for (int qi = tid; qi < nquads; qi += stride) {
        // two independent float4 loads (front-batched -> MLP=2)
        float4 xA = x4[2*qi + 0];
        float4 xB = x4[2*qi + 1];

        // four independent layer-1 chains (16 tanh batched)
        ull g0[4], g1[4], g2[4], g3[4];
        layer1(xA.x, xA.y, p, g0);
        layer1(xA.z, xA.w, p, g1);
        layer1(xB.x, xB.y, p, g2);
        layer1(xB.z, xB.w, p, g3);

        // two independent epilogues
        float2 rA = epilogue(g0, g1, p);
        float2 rB = epilogue(g2, g3, p);

        out2[2*qi + 0] = rA;
        out2[2*qi + 1] = rB;
    }

    // leftover odd pair (not hit for B = 8388608, kept for safety)
    if ((npairs & 1) && tid == 0) {
        int pi = npairs - 1;
        float4 xx = x4[pi];
        ull gA[4], gB[4];
        layer1(xx.x, xx.y, p, gA);
        layer1(xx.z, xx.w, p, gB);
        out2[pi] = epilogue(gA, gB, p);
    }

    // odd-row tail (not hit for B = 8388608, kept for safety)
    if ((nrows & 1) && tid == 0) {
        const float2* x2 = reinterpret_cast<const float2*>(x4);
        float2 xr = x2[nrows - 1];
        ull gA[4], gB[4];
        layer1(xr.x, xr.y, p, gA);
        layer1(xr.x, xr.y, p, gB);
        float2 r = epilogue(gA, gB, p);
        reinterpret_cast<float*>(out2)[nrows - 1] = r.x;
    }
}

extern "C" void kernel_launch(void* const* d_in, const int* in_sizes, int n_in,
                              void* d_out, int out_size)
{
    const float4* x4 = (const float4*)d_in[0];
    const float* W1 = (const float*)d_in[1];
    const float* b1 = (const float*)d_in[2];
    const float* a1 = (const float*)d_in[3];
    const float* c1 = (const float*)d_in[4];
    const float* W2 = (const float*)d_in[5];
    const float* b2 = (const float*)d_in[6];
    const float* a2 = (const float*)d_in[7];
    const float* c2 = (const float*)d_in[8];
    const float* W3 = (const float*)d_in[9];
    const float* b3 = (const float*)d_in[10];

    int nrows = in_sizes[0] / 2;   // x is [B, 2]
    int npairs = nrows / 2;

    const int threads = 128;
    const int blocks = 1776;       // 148 SMs * 12; grid-stride over quads

    moth_mlp_kernel<<<blocks, threads>>>(x4, W1, b1, a1, c1, W2, b2, a2, c2, W3, b3,
                                         (float2*)d_out, npairs, nrows);
}

// round 11
// speedup vs baseline: 2.7724x; 1.0082x over previous
#include <cuda_runtime.h>

typedef unsigned long long ull;

__device__ __forceinline__ float fast_tanh(float t) {
    float r;
    asm("tanh.approx.f32 %0, %1;" : "=f"(r) : "f"(t));
    return r;
}
__device__ __forceinline__ ull pack2(float lo, float hi) {
    ull r;
    asm("mov.b64 %0, {%1, %2};" : "=l"(r) : "f"(lo), "f"(hi));
    return r;
}
__device__ __forceinline__ ull splat2(float v) {
    ull r;
    asm("mov.b64 %0, {%1, %1};" : "=l"(r) : "f"(v));
    return r;
}
__device__ __forceinline__ void unpack2(ull v, float& lo, float& hi) {
    asm("mov.b64 {%0, %1}, %2;" : "=f"(lo), "=f"(hi) : "l"(v));
}
__device__ __forceinline__ ull ffma2(ull a, ull b, ull c) {
    ull d;
    asm("fma.rn.f32x2 %0, %1, %2, %3;" : "=l"(d) : "l"(a), "l"(b), "l"(c));
    return d;
}
__device__ __forceinline__ ull fmul2(ull a, ull b) {
    ull d;
    asm("mul.rn.f32x2 %0, %1, %2;" : "=l"(d) : "l"(a), "l"(b));
    return d;
}
__device__ __forceinline__ ull fadd2(ull a, ull b) {
    ull d;
    asm("add.rn.f32x2 %0, %1, %2;" : "=l"(d) : "l"(a), "l"(b));
    return d;
}

// All c-scalings folded:
//   layer1 computes y_i = 0.5*c1_i*h_i directly (tanh arg, no mul needed)
//   g'_i = y_i * sigma_i ; the (2/c1_i) recovery + a1_i + 0.5*c2_j folded into w2
//   layer2 accumulates v_j = 0.5*c2_j*z_j directly (tanh arg, no mul needed)
//   w3'_j = 2*a2_j*W3_j/c2_j recovers z_j*sigma_j contribution
struct Pr {
    ull w1a[4], w1b[4], b1[4];          // layer-1, pre-scaled by 0.5*c1 (packed over feature pairs)
    ull w2[4][4];                       // w2[j][q] lanes i=2q,2q+1: c2_j*a1_i*W2[i][j]/c1_i
    ull vb[4];                          // pack(0.5*c2_j*b2_j, 0)  -- accA init
    ull w3s[4];                         // splat(2*a2_j*W3_j/c2_j)
    ull b3s, half2;                     // splat(b3), splat(0.5)
};

// layer 1 for one row: produce g'[4] (8 features as 4 f32x2 pairs)
__device__ __forceinline__ void layer1(float x0, float x1, const Pr& p, ull g[4]) {
    ull x0p = splat2(x0), x1p = splat2(x1);
#pragma unroll
    for (int q = 0; q < 4; q++) {
        ull y = ffma2(x0p, p.w1a[q], ffma2(x1p, p.w1b[q], p.b1[q]));  // y = 0.5*c1*h
        float t0, t1; unpack2(y, t0, t1);
        ull tp = pack2(fast_tanh(t0), fast_tanh(t1));
        ull sp = ffma2(tp, p.half2, p.half2);    // sigmoid(c1*h) = 0.5*tanh(y) + 0.5
        g[q] = fmul2(y, sp);                     // g' = y * sigma  (recovery folded into w2)
    }
}

// epilogue for one row-pair: layer2 + layer3, packed over (rowA, rowB)
__device__ __forceinline__ float2 epilogue(const ull gA[4], const ull gB[4], const Pr& p) {
    ull op = p.b3s;                              // packed output accumulator (rowA, rowB)
#pragma unroll
    for (int j = 0; j < 4; j++) {
        ull accA = ffma2(gA[0], p.w2[j][0], p.vb[j]);   // bias folded into init
        ull accB = fmul2(gB[0], p.w2[j][0]);
#pragma unroll
        for (int q = 1; q < 4; q++) {
            accA = ffma2(gA[q], p.w2[j][q], accA);
            accB = ffma2(gB[q], p.w2[j][q], accB);
        }
        float alo, ahi, blo, bhi;
        unpack2(accA, alo, ahi);
        unpack2(accB, blo, bhi);
        ull vp = fadd2(pack2(alo, blo), pack2(ahi, bhi));   // v = 0.5*c2*z  (tanh arg)
        float t0, t1; unpack2(vp, t0, t1);
        ull tp = pack2(fast_tanh(t0), fast_tanh(t1));
        ull sp = ffma2(tp, p.half2, p.half2);
        op = ffma2(fmul2(vp, sp), p.w3s[j], op); // o += w3' * v * sigma
    }
    float oA, oB; unpack2(op, oA, oB);
    return make_float2(oA, oB);
}

__global__ __launch_bounds__(128)
void moth_mlp_kernel(const float4* __restrict__ x4,
                     const float* __restrict__ W1, const float* __restrict__ b1,
                     const float* __restrict__ a1, const float* __restrict__ c1,
                     const float* __restrict__ W2, const float* __restrict__ b2,
                     const float* __restrict__ a2, const float* __restrict__ c2,
                     const float* __restrict__ W3, const float* __restrict__ b3,
                     float2* __restrict__ out2,
                     int npairs, int nrows)
{
    Pr p;
#pragma unroll
    for (int q = 0; q < 4; q++) {
        int i0 = 2*q, i1 = 2*q + 1;
        float s0 = 0.5f * c1[i0], s1 = 0.5f * c1[i1];
        p.w1a[q] = pack2(s0 * W1[i0],     s1 * W1[i1]);
        p.w1b[q] = pack2(s0 * W1[8 + i0], s1 * W1[8 + i1]);
        p.b1[q]  = pack2(s0 * b1[i0],     s1 * b1[i1]);
    }
#pragma unroll
    for (int j = 0; j < 4; j++) {
        float c2j = c2[j];
#pragma unroll
        for (int q = 0; q < 4; q++) {
            int i0 = 2*q, i1 = 2*q + 1;
            p.w2[j][q] = pack2(c2j * a1[i0] * W2[i0*4 + j] * __fdividef(1.f, c1[i0]),
                               c2j * a1[i1] * W2[i1*4 + j] * __fdividef(1.f, c1[i1]));
        }
        p.vb[j]  = pack2(0.5f * c2j * b2[j], 0.0f);
        p.w3s[j] = splat2(2.0f * a2[j] * W3[j] * __fdividef(1.f, c2j));
    }
    p.b3s   = splat2(b3[0]);
    p.half2 = splat2(0.5f);

    const int stride = gridDim.x * blockDim.x;
    int tid = blockIdx.x * blockDim.x + threadIdx.x;

    int nquads = npairs >> 1;          // 2 pairs (4 rows) per iteration

    for (int qi = tid; qi < nquads; qi += stride) {
        // two independent float4 loads (front-batched -> MLP=2)
        float4 xA = x4[2*qi + 0];
        float4 xB = x4[2*qi + 1];

        // four independent layer-1 chains (16 tanh batched)
        ull g0[4], g1[4], g2[4], g3[4];
        layer1(xA.x, xA.y, p, g0);
        layer1(xA.z, xA.w, p, g1);
        layer1(xB.x, xB.y, p, g2);
        layer1(xB.z, xB.w, p, g3);

        // two independent epilogues
        float2 rA = epilogue(g0, g1, p);
        float2 rB = epilogue(g2, g3, p);

        out2[2*qi + 0] = rA;
        out2[2*qi + 1] = rB;
    }

    // leftover odd pair (not hit for B = 8388608, kept for safety)
    if ((npairs & 1) && tid == 0) {
        int pi = npairs - 1;
        float4 xx = x4[pi];
        ull gA[4], gB[4];
        layer1(xx.x, xx.y, p, gA);
        layer1(xx.z, xx.w, p, gB);
        out2[pi] = epilogue(gA, gB, p);
    }

    // odd-row tail (not hit for B = 8388608, kept for safety)
    if ((nrows & 1) && tid == 0) {
        const float2* x2 = reinterpret_cast<const float2*>(x4);
        float2 xr = x2[nrows - 1];
        ull gA[4], gB[4];
        layer1(xr.x, xr.y, p, gA);
        layer1(xr.x, xr.y, p, gB);
        float2 r = epilogue(gA, gB, p);
        reinterpret_cast<float*>(out2)[nrows - 1] = r.x;
    }
}

extern "C" void kernel_launch(void* const* d_in, const int* in_sizes, int n_in,
                              void* d_out, int out_size)
{
    const float4* x4 = (const float4*)d_in[0];
    const float* W1 = (const float*)d_in[1];
    const float* b1 = (const float*)d_in[2];
    const float* a1 = (const float*)d_in[3];
    const float* c1 = (const float*)d_in[4];
    const float* W2 = (const float*)d_in[5];
    const float* b2 = (const float*)d_in[6];
    const float* a2 = (const float*)d_in[7];
    const float* c2 = (const float*)d_in[8];
    const float* W3 = (const float*)d_in[9];
    const float* b3 = (const float*)d_in[10];

    int nrows = in_sizes[0] / 2;   // x is [B, 2]
    int npairs = nrows / 2;

    const int threads = 128;
    const int blocks = 1776;       // 148 SMs * 12; grid-stride over quads

    moth_mlp_kernel<<<blocks, threads>>>(x4, W1, b1, a1, c1, W2, b2, a2, c2, W3, b3,
                                         (float2*)d_out, npairs, nrows);
}

// round 12
// speedup vs baseline: 2.9347x; 1.0585x over previous
#include <cuda_runtime.h>

typedef unsigned long long ull;

__device__ __forceinline__ float fast_tanh(float t) {
    float r;
    asm("tanh.approx.f32 %0, %1;" : "=f"(r) : "f"(t));
    return r;
}
__device__ __forceinline__ ull pack2(float lo, float hi) {
    ull r;
    asm("mov.b64 %0, {%1, %2};" : "=l"(r) : "f"(lo), "f"(hi));
    return r;
}
__device__ __forceinline__ ull splat2(float v) {
    ull r;
    asm("mov.b64 %0, {%1, %1};" : "=l"(r) : "f"(v));
    return r;
}
__device__ __forceinline__ void unpack2(ull v, float& lo, float& hi) {
    asm("mov.b64 {%0, %1}, %2;" : "=f"(lo), "=f"(hi) : "l"(v));
}
__device__ __forceinline__ ull ffma2(ull a, ull b, ull c) {
    ull d;
    asm("fma.rn.f32x2 %0, %1, %2, %3;" : "=l"(d) : "l"(a), "l"(b), "l"(c));
    return d;
}
__device__ __forceinline__ ull fadd2(ull a, ull b) {
    ull d;
    asm("add.rn.f32x2 %0, %1, %2;" : "=l"(d) : "l"(a), "l"(b));
    return d;
}

// All scalings folded; sigmoid-affine fused into FMA:
//   layer1: y_i = 0.5*c1_i*h_i  (tanh arg, weights pre-scaled)
//           g''_i = fma(y, tanh(y), y) = 2*y*sigmoid(c1*h)   [the 2 folded into w2]
//   layer2: v_j = 0.5*c2_j*z_j  (accumulated directly; bias in BOTH acc inits)
//           contribution = w3'' * fma(v, tanh(v), v),  w3'' = a2*W3/c2
struct Pr {
    ull w1a[4], w1b[4], b1[4];          // layer-1, pre-scaled by 0.5*c1 (packed over feature pairs)
    ull w2[4][4];                       // w2[j][q] lanes i=2q,2q+1: 0.5*c2_j*a1_i*W2[i][j]/c1_i
    ull vb[4];                          // pack(0.5*c2_j*b2_j, 0)  -- lane-sum yields bias once per row
    ull w3s[4];                         // splat(a2_j*W3_j/c2_j)
    ull b3s;                            // splat(b3)
};

// layer 1 for one row: produce g''[4] (8 features as 4 f32x2 pairs)
__device__ __forceinline__ void layer1(float x0, float x1, const Pr& p, ull g[4]) {
    ull x0p = splat2(x0), x1p = splat2(x1);
#pragma unroll
    for (int q = 0; q < 4; q++) {
        ull y = ffma2(x0p, p.w1a[q], ffma2(x1p, p.w1b[q], p.b1[q]));  // y = 0.5*c1*h
        float t0, t1; unpack2(y, t0, t1);
        ull tp = pack2(fast_tanh(t0), fast_tanh(t1));
        g[q] = ffma2(y, tp, y);                  // y*(1+tanh) = 2*y*sigma  (0.5 folded into w2)
    }
}

// epilogue for one row-pair: layer2 + layer3, packed over (rowA, rowB)
__device__ __forceinline__ float2 epilogue(const ull gA[4], const ull gB[4], const Pr& p) {
    ull op = p.b3s;                              // packed output accumulator (rowA, rowB)
#pragma unroll
    for (int j = 0; j < 4; j++) {
        ull accA = ffma2(gA[0], p.w2[j][0], p.vb[j]);   // bias folded into BOTH inits
        ull accB = ffma2(gB[0], p.w2[j][0], p.vb[j]);   // (lane-sum adds it exactly once per row)
#pragma unroll
        for (int q = 1; q < 4; q++) {
            accA = ffma2(gA[q], p.w2[j][q], accA);
            accB = ffma2(gB[q], p.w2[j][q], accB);
        }
        float alo, ahi, blo, bhi;
        unpack2(accA, alo, ahi);
        unpack2(accB, blo, bhi);
        ull vp = fadd2(pack2(alo, blo), pack2(ahi, bhi));   // v = 0.5*c2*z  (rowA, rowB)
        float t0, t1; unpack2(vp, t0, t1);
        ull tp = pack2(fast_tanh(t0), fast_tanh(t1));
        op = ffma2(ffma2(vp, tp, vp), p.w3s[j], op);  // o += w3'' * v*(1+tanh) = a2*W3*z*sigma
    }
    float oA, oB; unpack2(op, oA, oB);
    return make_float2(oA, oB);
}

__global__ __launch_bounds__(128)
void moth_mlp_kernel(const float4* __restrict__ x4,
                     const float* __restrict__ W1, const float* __restrict__ b1,
                     const float* __restrict__ a1, const float* __restrict__ c1,
                     const float* __restrict__ W2, const float* __restrict__ b2,
                     const float* __restrict__ a2, const float* __restrict__ c2,
                     const float* __restrict__ W3, const float* __restrict__ b3,
                     float2* __restrict__ out2,
                     int npairs, int nrows)
{
    Pr p;
#pragma unroll
    for (int q = 0; q < 4; q++) {
        int i0 = 2*q, i1 = 2*q + 1;
        float s0 = 0.5f * c1[i0], s1 = 0.5f * c1[i1];
        p.w1a[q] = pack2(s0 * W1[i0],     s1 * W1[i1]);
        p.w1b[q] = pack2(s0 * W1[8 + i0], s1 * W1[8 + i1]);
        p.b1[q]  = pack2(s0 * b1[i0],     s1 * b1[i1]);
    }
#pragma unroll
    for (int j = 0; j < 4; j++) {
        float c2j = c2[j];
#pragma unroll
        for (int q = 0; q < 4; q++) {
            int i0 = 2*q, i1 = 2*q + 1;
            p.w2[j][q] = pack2(0.5f * c2j * a1[i0] * W2[i0*4 + j] * __fdividef(1.f, c1[i0]),
                               0.5f * c2j * a1[i1] * W2[i1*4 + j] * __fdividef(1.f, c1[i1]));
        }
        p.vb[j]  = pack2(0.5f * c2j * b2[j], 0.0f);
        p.w3s[j] = splat2(a2[j] * W3[j] * __fdividef(1.f, c2j));
    }
    p.b3s = splat2(b3[0]);

    const int stride = gridDim.x * blockDim.x;
    int tid = blockIdx.x * blockDim.x + threadIdx.x;

    int nquads = npairs >> 1;          // 2 pairs (4 rows) per iteration

    for (int qi = tid; qi < nquads; qi += stride) {
        // two independent float4 loads (front-batched -> MLP=2)
        float4 xA = x4[2*qi + 0];
        float4 xB = x4[2*qi + 1];

        // four independent layer-1 chains (16 tanh batched)
        ull g0[4], g1[4], g2[4], g3[4];
        layer1(xA.x, xA.y, p, g0);
        layer1(xA.z, xA.w, p, g1);
        layer1(xB.x, xB.y, p, g2);
        layer1(xB.z, xB.w, p, g3);

        // two independent epilogues
        float2 rA = epilogue(g0, g1, p);
        float2 rB = epilogue(g2, g3, p);

        out2[2*qi + 0] = rA;
        out2[2*qi + 1] = rB;
    }

    // leftover odd pair (not hit for B = 8388608, kept for safety)
    if ((npairs & 1) && tid == 0) {
        int pi = npairs - 1;
        float4 xx = x4[pi];
        ull gA[4], gB[4];
        layer1(xx.x, xx.y, p, gA);
        layer1(xx.z, xx.w, p, gB);
        out2[pi] = epilogue(gA, gB, p);
    }

    // odd-row tail (not hit for B = 8388608, kept for safety)
    if ((nrows & 1) && tid == 0) {
        const float2* x2 = reinterpret_cast<const float2*>(x4);
        float2 xr = x2[nrows - 1];
        ull gA[4], gB[4];
        layer1(xr.x, xr.y, p, gA);
        layer1(xr.x, xr.y, p, gB);
        float2 r = epilogue(gA, gB, p);
        reinterpret_cast<float*>(out2)[nrows - 1] = r.x;
    }
}

extern "C" void kernel_launch(void* const* d_in, const int* in_sizes, int n_in,
                              void* d_out, int out_size)
{
    const float4* x4 = (const float4*)d_in[0];
    const float* W1 = (const float*)d_in[1];
    const float* b1 = (const float*)d_in[2];
    const float* a1 = (const float*)d_in[3];
    const float* c1 = (const float*)d_in[4];
    const float* W2 = (const float*)d_in[5];
    const float* b2 = (const float*)d_in[6];
    const float* a2 = (const float*)d_in[7];
    const float* c2 = (const float*)d_in[8];
    const float* W3 = (const float*)d_in[9];
    const float* b3 = (const float*)d_in[10];

    int nrows = in_sizes[0] / 2;   // x is [B, 2]
    int npairs = nrows / 2;

    const int threads = 128;
    const int blocks = 1184;       // 148 SMs * 8 resident blocks: one clean wave

    moth_mlp_kernel<<<blocks, threads>>>(x4, W1, b1, a1, c1, W2, b2, a2, c2, W3, b3,
                                         (float2*)d_out, npairs, nrows);
}

// round 13
// speedup vs baseline: 2.9718x; 1.0126x over previous
#include <cuda_runtime.h>

typedef unsigned long long ull;

__device__ __forceinline__ float fast_tanh(float t) {
    float r;
    asm("tanh.approx.f32 %0, %1;" : "=f"(r) : "f"(t));
    return r;
}
__device__ __forceinline__ ull pack2(float lo, float hi) {
    ull r;
    asm("mov.b64 %0, {%1, %2};" : "=l"(r) : "f"(lo), "f"(hi));
    return r;
}
__device__ __forceinline__ ull splat2(float v) {
    ull r;
    asm("mov.b64 %0, {%1, %1};" : "=l"(r) : "f"(v));
    return r;
}
__device__ __forceinline__ void unpack2(ull v, float& lo, float& hi) {
    asm("mov.b64 {%0, %1}, %2;" : "=f"(lo), "=f"(hi) : "l"(v));
}
__device__ __forceinline__ ull ffma2(ull a, ull b, ull c) {
    ull d;
    asm("fma.rn.f32x2 %0, %1, %2, %3;" : "=l"(d) : "l"(a), "l"(b), "l"(c));
    return d;
}
__device__ __forceinline__ ull fadd2(ull a, ull b) {
    ull d;
    asm("add.rn.f32x2 %0, %1, %2;" : "=l"(d) : "l"(a), "l"(b));
    return d;
}

// All scalings folded; sigmoid-affine fused into FMA:
//   layer1: y_i = 0.5*c1_i*h_i  (tanh arg, weights pre-scaled)
//           g''_i = fma(y, tanh(y), y) = 2*y*sigmoid(c1*h)   [the 2 folded into w2]
//   layer2: v_j = 0.5*c2_j*z_j  (accumulated directly; bias in BOTH acc inits)
//           contribution = w3'' * fma(v, tanh(v), v),  w3'' = a2*W3/c2
struct Pr {
    ull w1a[4], w1b[4], b1[4];          // layer-1, pre-scaled by 0.5*c1 (packed over feature pairs)
    ull w2[4][4];                       // w2[j][q] lanes i=2q,2q+1: 0.5*c2_j*a1_i*W2[i][j]/c1_i
    ull vb[4];                          // pack(0.5*c2_j*b2_j, 0)  -- lane-sum yields bias once per row
    ull w3s[4];                         // splat(a2_j*W3_j/c2_j)
    ull b3s;                            // splat(b3)
};

// layer 1 for one row: produce g''[4] (8 features as 4 f32x2 pairs)
__device__ __forceinline__ void layer1(float x0, float x1, const Pr& p, ull g[4]) {
    ull x0p = splat2(x0), x1p = splat2(x1);
#pragma unroll
    for (int q = 0; q < 4; q++) {
        ull y = ffma2(x0p, p.w1a[q], ffma2(x1p, p.w1b[q], p.b1[q]));  // y = 0.5*c1*h
        float t0, t1; unpack2(y, t0, t1);
        ull tp = pack2(fast_tanh(t0), fast_tanh(t1));
        g[q] = ffma2(y, tp, y);                  // y*(1+tanh) = 2*y*sigma  (0.5 folded into w2)
    }
}

// epilogue for one row-pair: layer2 + layer3, packed over (rowA, rowB)
__device__ __forceinline__ float2 epilogue(const ull gA[4], const ull gB[4], const Pr& p) {
    ull op = p.b3s;                              // packed output accumulator (rowA, rowB)
#pragma unroll
    for (int j = 0; j < 4; j++) {
        ull accA = ffma2(gA[0], p.w2[j][0], p.vb[j]);   // bias folded into BOTH inits
        ull accB = ffma2(gB[0], p.w2[j][0], p.vb[j]);   // (lane-sum adds it exactly once per row)
#pragma unroll
        for (int q = 1; q < 4; q++) {
            accA = ffma2(gA[q], p.w2[j][q], accA);
            accB = ffma2(gB[q], p.w2[j][q], accB);
        }
        float alo, ahi, blo, bhi;
        unpack2(accA, alo, ahi);
        unpack2(accB, blo, bhi);
        ull vp = fadd2(pack2(alo, blo), pack2(ahi, bhi));   // v = 0.5*c2*z  (rowA, rowB)
        float t0, t1; unpack2(vp, t0, t1);
        ull tp = pack2(fast_tanh(t0), fast_tanh(t1));
        op = ffma2(ffma2(vp, tp, vp), p.w3s[j], op);  // o += w3'' * v*(1+tanh) = a2*W3*z*sigma
    }
    float oA, oB; unpack2(op, oA, oB);
    return make_float2(oA, oB);
}

__global__ __launch_bounds__(128, 8)   // cap 64 regs -> 8 blocks/SM (50% occ)
void moth_mlp_kernel(const float4* __restrict__ x4,
                     const float* __restrict__ W1, const float* __restrict__ b1,
                     const float* __restrict__ a1, const float* __restrict__ c1,
                     const float* __restrict__ W2, const float* __restrict__ b2,
                     const float* __restrict__ a2, const float* __restrict__ c2,
                     const float* __restrict__ W3, const float* __restrict__ b3,
                     float4* __restrict__ out4,
                     int npairs, int nrows)
{
    Pr p;
#pragma unroll
    for (int q = 0; q < 4; q++) {
        int i0 = 2*q, i1 = 2*q + 1;
        float s0 = 0.5f * c1[i0], s1 = 0.5f * c1[i1];
        p.w1a[q] = pack2(s0 * W1[i0],     s1 * W1[i1]);
        p.w1b[q] = pack2(s0 * W1[8 + i0], s1 * W1[8 + i1]);
        p.b1[q]  = pack2(s0 * b1[i0],     s1 * b1[i1]);
    }
#pragma unroll
    for (int j = 0; j < 4; j++) {
        float c2j = c2[j];
#pragma unroll
        for (int q = 0; q < 4; q++) {
            int i0 = 2*q, i1 = 2*q + 1;
            p.w2[j][q] = pack2(0.5f * c2j * a1[i0] * W2[i0*4 + j] * __fdividef(1.f, c1[i0]),
                               0.5f * c2j * a1[i1] * W2[i1*4 + j] * __fdividef(1.f, c1[i1]));
        }
        p.vb[j]  = pack2(0.5f * c2j * b2[j], 0.0f);
        p.w3s[j] = splat2(a2[j] * W3[j] * __fdividef(1.f, c2j));
    }
    p.b3s = splat2(b3[0]);

    const int stride = gridDim.x * blockDim.x;
    int tid = blockIdx.x * blockDim.x + threadIdx.x;

    int nquads = npairs >> 1;          // 2 pairs (4 rows) per iteration

    for (int qi = tid; qi < nquads; qi += stride) {
        // two independent float4 loads (front-batched -> MLP=2)
        float4 xA = x4[2*qi + 0];
        float4 xB = x4[2*qi + 1];

        // four independent layer-1 chains (16 tanh batched)
        ull g0[4], g1[4], g2[4], g3[4];
        layer1(xA.x, xA.y, p, g0);
        layer1(xA.z, xA.w, p, g1);
        layer1(xB.x, xB.y, p, g2);
        layer1(xB.z, xB.w, p, g3);

        // two independent epilogues; single STG.128 for 4 outputs
        float2 rA = epilogue(g0, g1, p);
        float2 rB = epilogue(g2, g3, p);

        out4[qi] = make_float4(rA.x, rA.y, rB.x, rB.y);
    }

    // leftover odd pair (not hit for B = 8388608, kept for safety)
    if ((npairs & 1) && tid == 0) {
        int pi = npairs - 1;
        float4 xx = x4[pi];
        ull gA[4], gB[4];
        layer1(xx.x, xx.y, p, gA);
        layer1(xx.z, xx.w, p, gB);
        float2 r = epilogue(gA, gB, p);
        reinterpret_cast<float2*>(out4)[pi] = r;
    }

    // odd-row tail (not hit for B = 8388608, kept for safety)
    if ((nrows & 1) && tid == 0) {
        const float2* x2 = reinterpret_cast<const float2*>(x4);
        float2 xr = x2[nrows - 1];
        ull gA[4], gB[4];
        layer1(xr.x, xr.y, p, gA);
        layer1(xr.x, xr.y, p, gB);
        float2 r = epilogue(gA, gB, p);
        reinterpret_cast<float*>(out4)[nrows - 1] = r.x;
    }
}

extern "C" void kernel_launch(void* const* d_in, const int* in_sizes, int n_in,
                              void* d_out, int out_size)
{
    const float4* x4 = (const float4*)d_in[0];
    const float* W1 = (const float*)d_in[1];
    const float* b1 = (const float*)d_in[2];
    const float* a1 = (const float*)d_in[3];
    const float* c1 = (const float*)d_in[4];
    const float* W2 = (const float*)d_in[5];
    const float* b2 = (const float*)d_in[6];
    const float* a2 = (const float*)d_in[7];
    const float* c2 = (const float*)d_in[8];
    const float* W3 = (const float*)d_in[9];
    const float* b3 = (const float*)d_in[10];

    int nrows = in_sizes[0] / 2;   // x is [B, 2]
    int npairs = nrows / 2;

    const int threads = 128;
    const int blocks = 1184;       // 148 SMs * 8 resident blocks: one clean wave

    moth_mlp_kernel<<<blocks, threads>>>(x4, W1, b1, a1, c1, W2, b2, a2, c2, W3, b3,
                                         (float4*)d_out, npairs, nrows);
}